// round 11
// baseline (speedup 1.0000x reference)
#include <cuda_runtime.h>
#include <cuda_fp16.h>
#include <math.h>
#include <stdint.h>

// ---------------- problem constants ----------------
#define BB 4
#define TT 256
#define UU 128
#define EE 512
#define DD 640
#define HH 512
#define VV 640
#define BT (BB*TT)          // 1024

// ---------------- device scratch ----------------
__device__ float g_enc_proj[BT * HH];        // [1024, 512]
__device__ float g_dec_proj[BB * UU * HH];   // [512, 512]
__device__ __half g_A_h[BT * UU * HH];       // fp16 tanh activations (134 MB)
__device__ __half g_W_h[VV * HH];            // W_out transposed [v][h], fp16

// ---------------- PTX helpers (baseline ISA only) ----------------
__device__ __forceinline__ uint32_t smem_u32(const void* p) {
    uint32_t a;
    asm("{ .reg .u64 t; cvta.to.shared.u64 t, %1; cvt.u32.u64 %0, t; }"
        : "=r"(a) : "l"(p));
    return a;
}
__device__ __forceinline__ float tanh_fast(float x) {
    float y;
    asm("tanh.approx.f32 %0, %1;" : "=f"(y) : "f"(x));
    return y;
}
__device__ __forceinline__ void cp_async16(uint32_t dst, const void* src) {
    asm volatile("cp.async.cg.shared.global [%0], [%1], 16;"
                 :: "r"(dst), "l"(src) : "memory");
}
__device__ __forceinline__ void cp_commit() {
    asm volatile("cp.async.commit_group;" ::: "memory");
}
template <int N>
__device__ __forceinline__ void cp_wait() {
    asm volatile("cp.async.wait_group %0;" :: "n"(N) : "memory");
}
__device__ __forceinline__ void ldsm_x4(uint32_t& r0, uint32_t& r1,
                                        uint32_t& r2, uint32_t& r3, uint32_t addr) {
    asm volatile("ldmatrix.sync.aligned.m8n8.x4.shared.b16 {%0,%1,%2,%3}, [%4];"
                 : "=r"(r0), "=r"(r1), "=r"(r2), "=r"(r3) : "r"(addr));
}
__device__ __forceinline__ void mma16816(float* c, uint32_t a0, uint32_t a1,
                                         uint32_t a2, uint32_t a3,
                                         uint32_t b0, uint32_t b1) {
    asm volatile(
        "mma.sync.aligned.m16n8k16.row.col.f32.f16.f16.f32 "
        "{%0,%1,%2,%3}, {%4,%5,%6,%7}, {%8,%9}, {%0,%1,%2,%3};"
        : "+f"(c[0]), "+f"(c[1]), "+f"(c[2]), "+f"(c[3])
        : "r"(a0), "r"(a1), "r"(a2), "r"(a3), "r"(b0), "r"(b1));
}

// ---------------------------------------------------------------------------
// proj: C[M,N] = A[M,K] @ W[K,N] (+ bias). fp32, 32x64 tile, 128 threads.
// ---------------------------------------------------------------------------
__global__ __launch_bounds__(128) void proj_kernel(
    const float* __restrict__ A, const float* __restrict__ W,
    const float* __restrict__ bias, float* __restrict__ C,
    int M, int N, int K)
{
    __shared__ float Ast[32][33];
    __shared__ float Ws[32][68];
    int tid = threadIdx.x;
    int tx = tid & 15, ty = tid >> 4;
    int m0 = blockIdx.y * 32, n0 = blockIdx.x * 64;

    float acc[4][4];
#pragma unroll
    for (int i = 0; i < 4; i++)
#pragma unroll
        for (int j = 0; j < 4; j++) acc[i][j] = 0.0f;

    for (int k0 = 0; k0 < K; k0 += 32) {
#pragma unroll
        for (int l = 0; l < 8; l++) {
            int idx = tid + l * 128;
            Ast[idx & 31][idx >> 5] = A[(m0 + (idx >> 5)) * K + k0 + (idx & 31)];
        }
#pragma unroll
        for (int l = 0; l < 16; l++) {
            int idx = tid + l * 128;
            Ws[idx >> 6][idx & 63] = W[(k0 + (idx >> 6)) * N + n0 + (idx & 63)];
        }
        __syncthreads();
#pragma unroll
        for (int k = 0; k < 32; k++) {
            float a[4], b[4];
#pragma unroll
            for (int i = 0; i < 4; i++) a[i] = Ast[k][ty * 4 + i];
#pragma unroll
            for (int j = 0; j < 4; j++) b[j] = Ws[k][tx * 4 + j];
#pragma unroll
            for (int i = 0; i < 4; i++)
#pragma unroll
                for (int j = 0; j < 4; j++)
                    acc[i][j] = fmaf(a[i], b[j], acc[i][j]);
        }
        __syncthreads();
    }
#pragma unroll
    for (int i = 0; i < 4; i++)
#pragma unroll
        for (int j = 0; j < 4; j++) {
            float v = acc[i][j];
            if (bias) v += bias[n0 + tx * 4 + j];
            C[(m0 + ty * 4 + i) * N + n0 + tx * 4 + j] = v;
        }
}

// ---------------------------------------------------------------------------
// prep_w: transpose + fp16 cast of W_out [H,V] -> [V,H]
// ---------------------------------------------------------------------------
__global__ __launch_bounds__(256) void prep_w_kernel(const float* __restrict__ W_out)
{
    int idx = blockIdx.x * 256 + threadIdx.x;
    if (idx >= VV * HH) return;
    int v = idx / HH, h = idx - v * HH;
    g_W_h[idx] = __float2half(W_out[h * VV + v]);
}

// ---------------------------------------------------------------------------
// act: grid (BT, 4), 256 threads. Each thread holds 8 enc floats in regs and
// covers 8 u's (unrolled, 8 independent dec loads in flight).
// 256 thr = 4 row-groups x 64 h-threads; block covers u in [gy*32, gy*32+32).
// ---------------------------------------------------------------------------
__global__ __launch_bounds__(256) void act_kernel()
{
    int bt = blockIdx.x;
    int b = bt >> 8;
    int ug = (threadIdx.x >> 6);            // 0..3 row group
    int u0 = blockIdx.y * 32 + ug * 8;      // 8 u's per thread
    int h = (threadIdx.x & 63) * 8;

    const float* ep = g_enc_proj + bt * HH + h;
    float4 e0 = *(const float4*)ep;
    float4 e1 = *(const float4*)(ep + 4);

    const float* dp = g_dec_proj + ((size_t)b * UU + u0) * HH + h;
    __half* ap = g_A_h + ((size_t)bt * UU + u0) * HH + h;

#pragma unroll
    for (int uu = 0; uu < 8; uu++) {
        float4 d0 = *(const float4*)(dp + (size_t)uu * HH);
        float4 d1 = *(const float4*)(dp + (size_t)uu * HH + 4);
        __half2 p0 = __floats2half2_rn(tanh_fast(e0.x + d0.x), tanh_fast(e0.y + d0.y));
        __half2 p1 = __floats2half2_rn(tanh_fast(e0.z + d0.z), tanh_fast(e0.w + d0.w));
        __half2 p2 = __floats2half2_rn(tanh_fast(e1.x + d1.x), tanh_fast(e1.y + d1.y));
        __half2 p3 = __floats2half2_rn(tanh_fast(e1.z + d1.z), tanh_fast(e1.w + d1.w));
        union { __half2 h2[4]; uint4 u4; } pk;
        pk.h2[0] = p0; pk.h2[1] = p1; pk.h2[2] = p2; pk.h2[3] = p3;
        *(uint4*)(ap + (size_t)uu * HH) = pk.u4;
    }
}

// ---------------------------------------------------------------------------
// joint GEMM (HMMA fp16): out[128u,128v] = A[128,512]@W^T + bias
// 4 warps (2x2), warp tile 64x64. K chunks of 64, 3-stage cp.async pipeline,
// XOR-swizzled 128B smem rows. 2 CTAs/SM.
// ---------------------------------------------------------------------------
#define KC 64
#define STAGE 32768      // A 16K + W 16K
#define OFF_W 16384
#define NSTAGE 3

__global__ __launch_bounds__(128, 2) void joint_hmma_kernel(
    const float* __restrict__ b_out, float* __restrict__ out)
{
    extern __shared__ char smem[];
    uint32_t sb = smem_u32(smem);
    int tid = threadIdx.x;
    int lane = tid & 31;
    int wid = tid >> 5;
    int bt = blockIdx.y;
    int v0 = blockIdx.x * 128;

    int wm = (wid & 1) * 64;     // warp m offset (u)
    int wn = (wid >> 1) * 64;    // warp n offset (v)

    const __half* Ag = g_A_h + (size_t)bt * UU * HH;
    const __half* Wg = g_W_h + (size_t)v0 * HH;

    float acc[4][8][4];
#pragma unroll
    for (int i = 0; i < 4; i++)
#pragma unroll
        for (int j = 0; j < 8; j++)
#pragma unroll
            for (int k = 0; k < 4; k++) acc[i][j][k] = 0.0f;

    auto fill = [&](int s, int k0) {
        uint32_t base = sb + s * STAGE;
#pragma unroll
        for (int l = 0; l < 8; l++) {
            int idx = tid + l * 128;      // 0..1023
            int r = idx >> 3;             // row 0..127
            int c = idx & 7;              // 16B chunk 0..7
            uint32_t doff = (uint32_t)(r * 128 + ((c ^ (r & 7)) << 4));
            cp_async16(base + doff,         Ag + (size_t)r * HH + k0 + c * 8);
            cp_async16(base + OFF_W + doff, Wg + (size_t)r * HH + k0 + c * 8);
        }
    };

    fill(0, 0);
    cp_commit();
    fill(1, KC);
    cp_commit();

#pragma unroll 1
    for (int c = 0; c < HH / KC; c++) {
        if (c + 2 < HH / KC) {
            fill((c + 2) % NSTAGE, (c + 2) * KC);
            cp_commit();
            cp_wait<2>();
        } else if (c + 2 == HH / KC) {
            cp_wait<1>();
        } else {
            cp_wait<0>();
        }
        __syncthreads();

        uint32_t sA = sb + (c % NSTAGE) * STAGE;
        uint32_t sW = sA + OFF_W;

#pragma unroll
        for (int s = 0; s < 4; s++) {
            uint32_t b0[8], b1[8];
#pragma unroll
            for (int jj = 0; jj < 4; jj++) {
                int row = wn + jj * 16 + ((lane >> 4) & 1) * 8 + (lane & 7);
                int chunk = 2 * s + ((lane >> 3) & 1);
                ldsm_x4(b0[jj * 2], b1[jj * 2], b0[jj * 2 + 1], b1[jj * 2 + 1],
                        sW + row * 128 + ((chunk ^ (row & 7)) << 4));
            }
#pragma unroll
            for (int mi = 0; mi < 4; mi++) {
                int row = wm + mi * 16 + ((lane >> 3) & 1) * 8 + (lane & 7);
                int chunk = 2 * s + (lane >> 4);
                uint32_t a0, a1, a2, a3;
                ldsm_x4(a0, a1, a2, a3,
                        sA + row * 128 + ((chunk ^ (row & 7)) << 4));
#pragma unroll
                for (int ni = 0; ni < 8; ni++)
                    mma16816(acc[mi][ni], a0, a1, a2, a3, b0[ni], b1[ni]);
            }
        }
        __syncthreads();
    }

    // ---- epilogue: bias + float2 stores straight from registers ----
    int gid = lane >> 2;
    int tig = lane & 3;
    float2 bias2[8];
#pragma unroll
    for (int ni = 0; ni < 8; ni++)
        bias2[ni] = *(const float2*)(b_out + v0 + wn + ni * 8 + tig * 2);

    float* obase = out + (size_t)bt * UU * VV + v0;
#pragma unroll
    for (int mi = 0; mi < 4; mi++) {
        int u0 = wm + mi * 16 + gid;
#pragma unroll
        for (int ni = 0; ni < 8; ni++) {
            int v = wn + ni * 8 + tig * 2;
            float2 r0 = make_float2(acc[mi][ni][0] + bias2[ni].x,
                                    acc[mi][ni][1] + bias2[ni].y);
            float2 r1 = make_float2(acc[mi][ni][2] + bias2[ni].x,
                                    acc[mi][ni][3] + bias2[ni].y);
            *(float2*)(obase + (size_t)u0 * VV + v) = r0;
            *(float2*)(obase + (size_t)(u0 + 8) * VV + v) = r1;
        }
    }
}

// ---------------------------------------------------------------------------
extern "C" void kernel_launch(void* const* d_in, const int* in_sizes, int n_in,
                              void* d_out, int out_size)
{
    const float* enc_out = (const float*)d_in[0];
    const float* dec_out = (const float*)d_in[1];
    const float* W_enc   = (const float*)d_in[2];
    const float* b_enc   = (const float*)d_in[3];
    const float* W_dec   = (const float*)d_in[4];
    const float* W_out   = (const float*)d_in[5];
    const float* b_out   = (const float*)d_in[6];
    float* out = (float*)d_out;

    cudaFuncSetAttribute(joint_hmma_kernel,
                         cudaFuncAttributeMaxDynamicSharedMemorySize, NSTAGE * STAGE);

    float* enc_proj_ptr = nullptr;
    float* dec_proj_ptr = nullptr;
    cudaGetSymbolAddress((void**)&enc_proj_ptr, g_enc_proj);
    cudaGetSymbolAddress((void**)&dec_proj_ptr, g_dec_proj);

    {
        dim3 grid(HH / 64, (BB * TT) / 32);   // (8, 32)
        proj_kernel<<<grid, 128>>>(enc_out, W_enc, b_enc, enc_proj_ptr, BB * TT, HH, EE);
    }
    {
        dim3 grid(HH / 64, (BB * UU) / 32);   // (8, 16)
        proj_kernel<<<grid, 128>>>(dec_out, W_dec, nullptr, dec_proj_ptr, BB * UU, HH, DD);
    }
    prep_w_kernel<<<(VV * HH + 255) / 256, 256>>>(W_out);
    {
        dim3 grid(BT, 4);
        act_kernel<<<grid, 256>>>();
    }
    {
        dim3 grid(VV / 128, BT);   // (5, 1024)
        joint_hmma_kernel<<<grid, 128, NSTAGE * STAGE>>>(b_out, out);
    }
}

// round 12
// speedup vs baseline: 1.0115x; 1.0115x over previous
#include <cuda_runtime.h>
#include <cuda_fp16.h>
#include <math.h>
#include <stdint.h>

// ---------------- problem constants ----------------
#define BB 4
#define TT 256
#define UU 128
#define EE 512
#define DD 640
#define HH 512
#define VV 640
#define BT (BB*TT)          // 1024

// ---------------- device scratch ----------------
__device__ float g_enc_proj[BT * HH];          // [1024, 512] fp32
__device__ __half g_dec_proj_h[BB * UU * HH];  // [512, 512] fp16
__device__ __half g_A_h[BT * UU * HH];         // fp16 tanh activations (134 MB)
__device__ __half g_W_h[VV * HH];              // W_out transposed [v][h], fp16

// ---------------- PTX helpers (baseline ISA only) ----------------
__device__ __forceinline__ uint32_t smem_u32(const void* p) {
    uint32_t a;
    asm("{ .reg .u64 t; cvta.to.shared.u64 t, %1; cvt.u32.u64 %0, t; }"
        : "=r"(a) : "l"(p));
    return a;
}
__device__ __forceinline__ float tanh_fast(float x) {
    float y;
    asm("tanh.approx.f32 %0, %1;" : "=f"(y) : "f"(x));
    return y;
}
__device__ __forceinline__ void cp_async16(uint32_t dst, const void* src) {
    asm volatile("cp.async.cg.shared.global [%0], [%1], 16;"
                 :: "r"(dst), "l"(src) : "memory");
}
__device__ __forceinline__ void cp_commit() {
    asm volatile("cp.async.commit_group;" ::: "memory");
}
template <int N>
__device__ __forceinline__ void cp_wait() {
    asm volatile("cp.async.wait_group %0;" :: "n"(N) : "memory");
}
__device__ __forceinline__ void ldsm_x4(uint32_t& r0, uint32_t& r1,
                                        uint32_t& r2, uint32_t& r3, uint32_t addr) {
    asm volatile("ldmatrix.sync.aligned.m8n8.x4.shared.b16 {%0,%1,%2,%3}, [%4];"
                 : "=r"(r0), "=r"(r1), "=r"(r2), "=r"(r3) : "r"(addr));
}
__device__ __forceinline__ void mma16816(float* c, uint32_t a0, uint32_t a1,
                                         uint32_t a2, uint32_t a3,
                                         uint32_t b0, uint32_t b1) {
    asm volatile(
        "mma.sync.aligned.m16n8k16.row.col.f32.f16.f16.f32 "
        "{%0,%1,%2,%3}, {%4,%5,%6,%7}, {%8,%9}, {%0,%1,%2,%3};"
        : "+f"(c[0]), "+f"(c[1]), "+f"(c[2]), "+f"(c[3])
        : "r"(a0), "r"(a1), "r"(a2), "r"(a3), "r"(b0), "r"(b1));
}

// ---------------------------------------------------------------------------
// proj: C = A[M,K] @ W[K,N] (+ bias). fp32 math, 32x64 tile, 128 threads.
// Output to fp32 (Cf) or fp16 (Ch) depending on which pointer is non-null.
// ---------------------------------------------------------------------------
__global__ __launch_bounds__(128) void proj_kernel(
    const float* __restrict__ A, const float* __restrict__ W,
    const float* __restrict__ bias, float* __restrict__ Cf,
    __half* __restrict__ Ch, int M, int N, int K)
{
    __shared__ float Ast[32][33];
    __shared__ float Ws[32][68];
    int tid = threadIdx.x;
    int tx = tid & 15, ty = tid >> 4;
    int m0 = blockIdx.y * 32, n0 = blockIdx.x * 64;

    float acc[4][4];
#pragma unroll
    for (int i = 0; i < 4; i++)
#pragma unroll
        for (int j = 0; j < 4; j++) acc[i][j] = 0.0f;

    for (int k0 = 0; k0 < K; k0 += 32) {
#pragma unroll
        for (int l = 0; l < 8; l++) {
            int idx = tid + l * 128;
            Ast[idx & 31][idx >> 5] = A[(m0 + (idx >> 5)) * K + k0 + (idx & 31)];
        }
#pragma unroll
        for (int l = 0; l < 16; l++) {
            int idx = tid + l * 128;
            Ws[idx >> 6][idx & 63] = W[(k0 + (idx >> 6)) * N + n0 + (idx & 63)];
        }
        __syncthreads();
#pragma unroll
        for (int k = 0; k < 32; k++) {
            float a[4], b[4];
#pragma unroll
            for (int i = 0; i < 4; i++) a[i] = Ast[k][ty * 4 + i];
#pragma unroll
            for (int j = 0; j < 4; j++) b[j] = Ws[k][tx * 4 + j];
#pragma unroll
            for (int i = 0; i < 4; i++)
#pragma unroll
                for (int j = 0; j < 4; j++)
                    acc[i][j] = fmaf(a[i], b[j], acc[i][j]);
        }
        __syncthreads();
    }
#pragma unroll
    for (int i = 0; i < 4; i++)
#pragma unroll
        for (int j = 0; j < 4; j++) {
            float v = acc[i][j];
            if (bias) v += bias[n0 + tx * 4 + j];
            int row = m0 + ty * 4 + i, col = n0 + tx * 4 + j;
            if (Cf) Cf[row * N + col] = v;
            else    Ch[row * N + col] = __float2half(v);
        }
}

// ---------------------------------------------------------------------------
// prep_w: transpose + fp16 cast of W_out [H,V] -> [V,H]
// ---------------------------------------------------------------------------
__global__ __launch_bounds__(256) void prep_w_kernel(const float* __restrict__ W_out)
{
    int idx = blockIdx.x * 256 + threadIdx.x;
    if (idx >= VV * HH) return;
    int v = idx / HH, h = idx - v * HH;
    g_W_h[idx] = __float2half(W_out[h * VV + v]);
}

// ---------------------------------------------------------------------------
// act: grid (BT, 4), 256 threads. enc fp32 in registers, dec read as fp16
// (halves read traffic); 8 u's per thread, unrolled for MLP.
// ---------------------------------------------------------------------------
__global__ __launch_bounds__(256) void act_kernel()
{
    int bt = blockIdx.x;
    int b = bt >> 8;
    int ug = (threadIdx.x >> 6);            // 0..3 row group
    int u0 = blockIdx.y * 32 + ug * 8;      // 8 u's per thread
    int h = (threadIdx.x & 63) * 8;

    const float* ep = g_enc_proj + bt * HH + h;
    float4 e0 = *(const float4*)ep;
    float4 e1 = *(const float4*)(ep + 4);

    const __half* dp = g_dec_proj_h + ((size_t)b * UU + u0) * HH + h;
    __half* ap = g_A_h + ((size_t)bt * UU + u0) * HH + h;

#pragma unroll
    for (int uu = 0; uu < 8; uu++) {
        union { uint4 u4; __half2 h2[4]; } din;
        din.u4 = *(const uint4*)(dp + (size_t)uu * HH);
        float2 d0 = __half22float2(din.h2[0]);
        float2 d1 = __half22float2(din.h2[1]);
        float2 d2 = __half22float2(din.h2[2]);
        float2 d3 = __half22float2(din.h2[3]);
        __half2 p0 = __floats2half2_rn(tanh_fast(e0.x + d0.x), tanh_fast(e0.y + d0.y));
        __half2 p1 = __floats2half2_rn(tanh_fast(e0.z + d1.x), tanh_fast(e0.w + d1.y));
        __half2 p2 = __floats2half2_rn(tanh_fast(e1.x + d2.x), tanh_fast(e1.y + d2.y));
        __half2 p3 = __floats2half2_rn(tanh_fast(e1.z + d3.x), tanh_fast(e1.w + d3.y));
        union { __half2 h2[4]; uint4 u4; } pk;
        pk.h2[0] = p0; pk.h2[1] = p1; pk.h2[2] = p2; pk.h2[3] = p3;
        *(uint4*)(ap + (size_t)uu * HH) = pk.u4;
    }
}

// ---------------------------------------------------------------------------
// joint GEMM (HMMA fp16): out[128u,128v] = A[128,512]@W^T + bias
// 4 warps (2x2), warp tile 64x64. K chunks of 64, 3-stage cp.async pipeline
// with a SINGLE __syncthreads per chunk (fill-after-barrier ordering).
// ---------------------------------------------------------------------------
#define KC 64
#define STAGE 32768      // A 16K + W 16K
#define OFF_W 16384
#define NSTAGE 3
#define NCHUNK (HH / KC) // 8

__global__ __launch_bounds__(128, 2) void joint_hmma_kernel(
    const float* __restrict__ b_out, float* __restrict__ out)
{
    extern __shared__ char smem[];
    uint32_t sb = smem_u32(smem);
    int tid = threadIdx.x;
    int lane = tid & 31;
    int wid = tid >> 5;
    int bt = blockIdx.y;
    int v0 = blockIdx.x * 128;

    int wm = (wid & 1) * 64;     // warp m offset (u)
    int wn = (wid >> 1) * 64;    // warp n offset (v)

    const __half* Ag = g_A_h + (size_t)bt * UU * HH;
    const __half* Wg = g_W_h + (size_t)v0 * HH;

    float acc[4][8][4];
#pragma unroll
    for (int i = 0; i < 4; i++)
#pragma unroll
        for (int j = 0; j < 8; j++)
#pragma unroll
            for (int k = 0; k < 4; k++) acc[i][j][k] = 0.0f;

    auto fill = [&](int s, int k0) {
        uint32_t base = sb + s * STAGE;
#pragma unroll
        for (int l = 0; l < 8; l++) {
            int idx = tid + l * 128;      // 0..1023
            int r = idx >> 3;             // row 0..127
            int c = idx & 7;              // 16B chunk 0..7
            uint32_t doff = (uint32_t)(r * 128 + ((c ^ (r & 7)) << 4));
            cp_async16(base + doff,         Ag + (size_t)r * HH + k0 + c * 8);
            cp_async16(base + OFF_W + doff, Wg + (size_t)r * HH + k0 + c * 8);
        }
    };

    fill(0, 0);
    cp_commit();
    fill(1, KC);
    cp_commit();

#pragma unroll 1
    for (int c = 0; c < NCHUNK; c++) {
        // wait for stage c's data (oldest pending group)
        if (c < NCHUNK - 1) cp_wait<1>(); else cp_wait<0>();
        __syncthreads();   // all warps: stage c ready AND done reading stage (c-1)%3
        if (c + 2 < NCHUNK) {
            fill((c + 2) % NSTAGE, (c + 2) * KC);  // writes (c+2)%3 != c%3, (c+1)%3
            cp_commit();
        }

        uint32_t sA = sb + (c % NSTAGE) * STAGE;
        uint32_t sW = sA + OFF_W;

#pragma unroll
        for (int s = 0; s < 4; s++) {
            uint32_t b0[8], b1[8];
#pragma unroll
            for (int jj = 0; jj < 4; jj++) {
                int row = wn + jj * 16 + ((lane >> 4) & 1) * 8 + (lane & 7);
                int chunk = 2 * s + ((lane >> 3) & 1);
                ldsm_x4(b0[jj * 2], b1[jj * 2], b0[jj * 2 + 1], b1[jj * 2 + 1],
                        sW + row * 128 + ((chunk ^ (row & 7)) << 4));
            }
#pragma unroll
            for (int mi = 0; mi < 4; mi++) {
                int row = wm + mi * 16 + ((lane >> 3) & 1) * 8 + (lane & 7);
                int chunk = 2 * s + (lane >> 4);
                uint32_t a0, a1, a2, a3;
                ldsm_x4(a0, a1, a2, a3,
                        sA + row * 128 + ((chunk ^ (row & 7)) << 4));
#pragma unroll
                for (int ni = 0; ni < 8; ni++)
                    mma16816(acc[mi][ni], a0, a1, a2, a3, b0[ni], b1[ni]);
            }
        }
    }

    // ---- epilogue: bias + float2 stores straight from registers ----
    int gid = lane >> 2;
    int tig = lane & 3;
    float2 bias2[8];
#pragma unroll
    for (int ni = 0; ni < 8; ni++)
        bias2[ni] = *(const float2*)(b_out + v0 + wn + ni * 8 + tig * 2);

    float* obase = out + (size_t)bt * UU * VV + v0;
#pragma unroll
    for (int mi = 0; mi < 4; mi++) {
        int u0 = wm + mi * 16 + gid;
#pragma unroll
        for (int ni = 0; ni < 8; ni++) {
            int v = wn + ni * 8 + tig * 2;
            float2 r0 = make_float2(acc[mi][ni][0] + bias2[ni].x,
                                    acc[mi][ni][1] + bias2[ni].y);
            float2 r1 = make_float2(acc[mi][ni][2] + bias2[ni].x,
                                    acc[mi][ni][3] + bias2[ni].y);
            *(float2*)(obase + (size_t)u0 * VV + v) = r0;
            *(float2*)(obase + (size_t)(u0 + 8) * VV + v) = r1;
        }
    }
}

// ---------------------------------------------------------------------------
extern "C" void kernel_launch(void* const* d_in, const int* in_sizes, int n_in,
                              void* d_out, int out_size)
{
    const float* enc_out = (const float*)d_in[0];
    const float* dec_out = (const float*)d_in[1];
    const float* W_enc   = (const float*)d_in[2];
    const float* b_enc   = (const float*)d_in[3];
    const float* W_dec   = (const float*)d_in[4];
    const float* W_out   = (const float*)d_in[5];
    const float* b_out   = (const float*)d_in[6];
    float* out = (float*)d_out;

    cudaFuncSetAttribute(joint_hmma_kernel,
                         cudaFuncAttributeMaxDynamicSharedMemorySize, NSTAGE * STAGE);

    float* enc_proj_ptr = nullptr;
    __half* dec_proj_ptr = nullptr;
    cudaGetSymbolAddress((void**)&enc_proj_ptr, g_enc_proj);
    cudaGetSymbolAddress((void**)&dec_proj_ptr, g_dec_proj_h);

    {
        dim3 grid(HH / 64, (BB * TT) / 32);   // (8, 32)
        proj_kernel<<<grid, 128>>>(enc_out, W_enc, b_enc, enc_proj_ptr, nullptr,
                                   BB * TT, HH, EE);
    }
    {
        dim3 grid(HH / 64, (BB * UU) / 32);   // (8, 16)
        proj_kernel<<<grid, 128>>>(dec_out, W_dec, nullptr, nullptr, dec_proj_ptr,
                                   BB * UU, HH, DD);
    }
    prep_w_kernel<<<(VV * HH + 255) / 256, 256>>>(W_out);
    {
        dim3 grid(BT, 4);
        act_kernel<<<grid, 256>>>();
    }
    {
        dim3 grid(VV / 128, BT);   // (5, 1024)
        joint_hmma_kernel<<<grid, 128, NSTAGE * STAGE>>>(b_out, out);
    }
}

// round 13
// speedup vs baseline: 1.1109x; 1.0983x over previous
#include <cuda_runtime.h>
#include <cuda_fp16.h>
#include <math.h>
#include <stdint.h>

// ---------------- problem constants ----------------
#define BB 4
#define TT 256
#define UU 128
#define EE 512
#define DD 640
#define HH 512
#define VV 640
#define BT (BB*TT)          // 1024

// ---------------- device scratch ----------------
__device__ float g_enc_proj[BT * HH];          // [1024, 512] fp32
__device__ __half g_dec_proj_h[BB * UU * HH];  // [512, 512] fp16
__device__ __half g_A_h[BT * UU * HH];         // fp16 tanh activations (134 MB)
__device__ __half g_W_h[VV * HH];              // W_out transposed [v][h], fp16

// ---------------- PTX helpers (baseline ISA only) ----------------
__device__ __forceinline__ uint32_t smem_u32(const void* p) {
    uint32_t a;
    asm("{ .reg .u64 t; cvta.to.shared.u64 t, %1; cvt.u32.u64 %0, t; }"
        : "=r"(a) : "l"(p));
    return a;
}
__device__ __forceinline__ float tanh_fast(float x) {
    float y;
    asm("tanh.approx.f32 %0, %1;" : "=f"(y) : "f"(x));
    return y;
}
__device__ __forceinline__ void cp_async16(uint32_t dst, const void* src) {
    asm volatile("cp.async.cg.shared.global [%0], [%1], 16;"
                 :: "r"(dst), "l"(src) : "memory");
}
__device__ __forceinline__ void cp_commit() {
    asm volatile("cp.async.commit_group;" ::: "memory");
}
template <int N>
__device__ __forceinline__ void cp_wait() {
    asm volatile("cp.async.wait_group %0;" :: "n"(N) : "memory");
}
__device__ __forceinline__ void ldsm_x4(uint32_t& r0, uint32_t& r1,
                                        uint32_t& r2, uint32_t& r3, uint32_t addr) {
    asm volatile("ldmatrix.sync.aligned.m8n8.x4.shared.b16 {%0,%1,%2,%3}, [%4];"
                 : "=r"(r0), "=r"(r1), "=r"(r2), "=r"(r3) : "r"(addr));
}
__device__ __forceinline__ void mma16816(float* c, uint32_t a0, uint32_t a1,
                                         uint32_t a2, uint32_t a3,
                                         uint32_t b0, uint32_t b1) {
    asm volatile(
        "mma.sync.aligned.m16n8k16.row.col.f32.f16.f16.f32 "
        "{%0,%1,%2,%3}, {%4,%5,%6,%7}, {%8,%9}, {%0,%1,%2,%3};"
        : "+f"(c[0]), "+f"(c[1]), "+f"(c[2]), "+f"(c[3])
        : "r"(a0), "r"(a1), "r"(a2), "r"(a3), "r"(b0), "r"(b1));
}

// ---------------------------------------------------------------------------
// prep_all: ONE launch, blockIdx.y selects work.
//   y in [0,32):  enc proj rows (32 u-rows each)   C -> g_enc_proj (fp32, +bias)
//   y in [32,48): dec proj rows                    C -> g_dec_proj_h (fp16)
//   y in [48,58): W_out [H,V] -> g_W_h [V,H] fp16 transpose cast
// 128 threads per block.
// ---------------------------------------------------------------------------
__global__ __launch_bounds__(128) void prep_all_kernel(
    const float* __restrict__ enc_out, const float* __restrict__ W_enc,
    const float* __restrict__ b_enc,
    const float* __restrict__ dec_out, const float* __restrict__ W_dec,
    const float* __restrict__ W_out)
{
    int gy = blockIdx.y;

    if (gy >= 48) {
        // ---- W transpose-cast: 10 y-blocks x 8 x-blocks, 4096 elems each ----
        int blk = (gy - 48) * 8 + blockIdx.x;      // 0..79
        int base = blk * 4096;                     // of VV*HH = 327680
#pragma unroll
        for (int l = 0; l < 32; l++) {
            int idx = base + threadIdx.x + l * 128;
            int v = idx / HH, h = idx - v * HH;
            g_W_h[idx] = __float2half(W_out[h * VV + v]);
        }
        return;
    }

    // ---- projection GEMM: 32x64 tile ----
    const float* A;
    const float* W;
    int M, K, m0;
    bool is_enc = (gy < 32);
    if (is_enc) { A = enc_out; W = W_enc; M = BT;      K = EE; m0 = gy * 32; }
    else        { A = dec_out; W = W_dec; M = BB * UU; K = DD; m0 = (gy - 32) * 32; }
    int n0 = blockIdx.x * 64;

    __shared__ float Ast[32][33];
    __shared__ float Ws[32][68];
    int tid = threadIdx.x;
    int tx = tid & 15, ty = tid >> 4;

    float acc[4][4];
#pragma unroll
    for (int i = 0; i < 4; i++)
#pragma unroll
        for (int j = 0; j < 4; j++) acc[i][j] = 0.0f;

    for (int k0 = 0; k0 < K; k0 += 32) {
#pragma unroll
        for (int l = 0; l < 8; l++) {
            int idx = tid + l * 128;
            Ast[idx & 31][idx >> 5] = A[(m0 + (idx >> 5)) * K + k0 + (idx & 31)];
        }
#pragma unroll
        for (int l = 0; l < 16; l++) {
            int idx = tid + l * 128;
            Ws[idx >> 6][idx & 63] = W[(k0 + (idx >> 6)) * HH + n0 + (idx & 63)];
        }
        __syncthreads();
#pragma unroll
        for (int k = 0; k < 32; k++) {
            float a[4], b[4];
#pragma unroll
            for (int i = 0; i < 4; i++) a[i] = Ast[k][ty * 4 + i];
#pragma unroll
            for (int j = 0; j < 4; j++) b[j] = Ws[k][tx * 4 + j];
#pragma unroll
            for (int i = 0; i < 4; i++)
#pragma unroll
                for (int j = 0; j < 4; j++)
                    acc[i][j] = fmaf(a[i], b[j], acc[i][j]);
        }
        __syncthreads();
    }

    if (is_enc) {
#pragma unroll
        for (int i = 0; i < 4; i++)
#pragma unroll
            for (int j = 0; j < 4; j++) {
                int col = n0 + tx * 4 + j;
                g_enc_proj[(m0 + ty * 4 + i) * HH + col] = acc[i][j] + b_enc[col];
            }
    } else {
#pragma unroll
        for (int i = 0; i < 4; i++)
#pragma unroll
            for (int j = 0; j < 4; j++)
                g_dec_proj_h[(m0 + ty * 4 + i) * HH + n0 + tx * 4 + j] =
                    __float2half(acc[i][j]);
    }
}

// ---------------------------------------------------------------------------
// act: grid (BT, 4), 256 threads. enc fp32 in registers, dec read as fp16.
// ---------------------------------------------------------------------------
__global__ __launch_bounds__(256) void act_kernel()
{
    int bt = blockIdx.x;
    int b = bt >> 8;
    int ug = (threadIdx.x >> 6);            // 0..3 row group
    int u0 = blockIdx.y * 32 + ug * 8;      // 8 u's per thread
    int h = (threadIdx.x & 63) * 8;

    const float* ep = g_enc_proj + bt * HH + h;
    float4 e0 = *(const float4*)ep;
    float4 e1 = *(const float4*)(ep + 4);

    const __half* dp = g_dec_proj_h + ((size_t)b * UU + u0) * HH + h;
    __half* ap = g_A_h + ((size_t)bt * UU + u0) * HH + h;

#pragma unroll
    for (int uu = 0; uu < 8; uu++) {
        union { uint4 u4; __half2 h2[4]; } din;
        din.u4 = *(const uint4*)(dp + (size_t)uu * HH);
        float2 d0 = __half22float2(din.h2[0]);
        float2 d1 = __half22float2(din.h2[1]);
        float2 d2 = __half22float2(din.h2[2]);
        float2 d3 = __half22float2(din.h2[3]);
        __half2 p0 = __floats2half2_rn(tanh_fast(e0.x + d0.x), tanh_fast(e0.y + d0.y));
        __half2 p1 = __floats2half2_rn(tanh_fast(e0.z + d1.x), tanh_fast(e0.w + d1.y));
        __half2 p2 = __floats2half2_rn(tanh_fast(e1.x + d2.x), tanh_fast(e1.y + d2.y));
        __half2 p3 = __floats2half2_rn(tanh_fast(e1.z + d3.x), tanh_fast(e1.w + d3.y));
        union { __half2 h2[4]; uint4 u4; } pk;
        pk.h2[0] = p0; pk.h2[1] = p1; pk.h2[2] = p2; pk.h2[3] = p3;
        *(uint4*)(ap + (size_t)uu * HH) = pk.u4;
    }
}

// ---------------------------------------------------------------------------
// joint GEMM (HMMA fp16): out[128u,128v] = A[128,512]@W^T + bias
// 4 warps (2x2), warp tile 64x64. KC=64, 3-stage cp.async, single sync/chunk.
// All 8 ldsm of a k16 step issued before its 128 MMAs.
// ---------------------------------------------------------------------------
#define KC 64
#define STAGE 32768      // A 16K + W 16K
#define OFF_W 16384
#define NSTAGE 3
#define NCHUNK (HH / KC) // 8

__global__ __launch_bounds__(128, 2) void joint_hmma_kernel(
    const float* __restrict__ b_out, float* __restrict__ out)
{
    extern __shared__ char smem[];
    uint32_t sb = smem_u32(smem);
    int tid = threadIdx.x;
    int lane = tid & 31;
    int wid = tid >> 5;
    int bt = blockIdx.y;
    int v0 = blockIdx.x * 128;

    int wm = (wid & 1) * 64;     // warp m offset (u)
    int wn = (wid >> 1) * 64;    // warp n offset (v)

    const __half* Ag = g_A_h + (size_t)bt * UU * HH;
    const __half* Wg = g_W_h + (size_t)v0 * HH;

    float acc[4][8][4];
#pragma unroll
    for (int i = 0; i < 4; i++)
#pragma unroll
        for (int j = 0; j < 8; j++)
#pragma unroll
            for (int k = 0; k < 4; k++) acc[i][j][k] = 0.0f;

    auto fill = [&](int s, int k0) {
        uint32_t base = sb + s * STAGE;
#pragma unroll
        for (int l = 0; l < 8; l++) {
            int idx = tid + l * 128;      // 0..1023
            int r = idx >> 3;             // row 0..127
            int c = idx & 7;              // 16B chunk 0..7
            uint32_t doff = (uint32_t)(r * 128 + ((c ^ (r & 7)) << 4));
            cp_async16(base + doff,         Ag + (size_t)r * HH + k0 + c * 8);
            cp_async16(base + OFF_W + doff, Wg + (size_t)r * HH + k0 + c * 8);
        }
    };

    fill(0, 0);
    cp_commit();
    fill(1, KC);
    cp_commit();

#pragma unroll 1
    for (int c = 0; c < NCHUNK; c++) {
        if (c < NCHUNK - 1) cp_wait<1>(); else cp_wait<0>();
        __syncthreads();
        if (c + 2 < NCHUNK) {
            fill((c + 2) % NSTAGE, (c + 2) * KC);
            cp_commit();
        }

        uint32_t sA = sb + (c % NSTAGE) * STAGE;
        uint32_t sW = sA + OFF_W;

#pragma unroll
        for (int s = 0; s < 4; s++) {
            // ---- issue ALL fragments for this k16 step first ----
            uint32_t b0[8], b1[8];
            uint32_t a[4][4];
#pragma unroll
            for (int jj = 0; jj < 4; jj++) {
                int row = wn + jj * 16 + ((lane >> 4) & 1) * 8 + (lane & 7);
                int chunk = 2 * s + ((lane >> 3) & 1);
                ldsm_x4(b0[jj * 2], b1[jj * 2], b0[jj * 2 + 1], b1[jj * 2 + 1],
                        sW + row * 128 + ((chunk ^ (row & 7)) << 4));
            }
#pragma unroll
            for (int mi = 0; mi < 4; mi++) {
                int row = wm + mi * 16 + ((lane >> 3) & 1) * 8 + (lane & 7);
                int chunk = 2 * s + (lane >> 4);
                ldsm_x4(a[mi][0], a[mi][1], a[mi][2], a[mi][3],
                        sA + row * 128 + ((chunk ^ (row & 7)) << 4));
            }
            // ---- then 128 MMAs ----
#pragma unroll
            for (int mi = 0; mi < 4; mi++)
#pragma unroll
                for (int ni = 0; ni < 8; ni++)
                    mma16816(acc[mi][ni], a[mi][0], a[mi][1], a[mi][2], a[mi][3],
                             b0[ni], b1[ni]);
        }
    }

    // ---- epilogue: bias + float2 stores straight from registers ----
    int gid = lane >> 2;
    int tig = lane & 3;
    float2 bias2[8];
#pragma unroll
    for (int ni = 0; ni < 8; ni++)
        bias2[ni] = *(const float2*)(b_out + v0 + wn + ni * 8 + tig * 2);

    float* obase = out + (size_t)bt * UU * VV + v0;
#pragma unroll
    for (int mi = 0; mi < 4; mi++) {
        int u0 = wm + mi * 16 + gid;
#pragma unroll
        for (int ni = 0; ni < 8; ni++) {
            int v = wn + ni * 8 + tig * 2;
            float2 r0 = make_float2(acc[mi][ni][0] + bias2[ni].x,
                                    acc[mi][ni][1] + bias2[ni].y);
            float2 r1 = make_float2(acc[mi][ni][2] + bias2[ni].x,
                                    acc[mi][ni][3] + bias2[ni].y);
            *(float2*)(obase + (size_t)u0 * VV + v) = r0;
            *(float2*)(obase + (size_t)(u0 + 8) * VV + v) = r1;
        }
    }
}

// ---------------------------------------------------------------------------
extern "C" void kernel_launch(void* const* d_in, const int* in_sizes, int n_in,
                              void* d_out, int out_size)
{
    const float* enc_out = (const float*)d_in[0];
    const float* dec_out = (const float*)d_in[1];
    const float* W_enc   = (const float*)d_in[2];
    const float* b_enc   = (const float*)d_in[3];
    const float* W_dec   = (const float*)d_in[4];
    const float* W_out   = (const float*)d_in[5];
    const float* b_out   = (const float*)d_in[6];
    float* out = (float*)d_out;

    cudaFuncSetAttribute(joint_hmma_kernel,
                         cudaFuncAttributeMaxDynamicSharedMemorySize, NSTAGE * STAGE);

    {
        // y: [0,32) enc proj, [32,48) dec proj, [48,58) W cast. x: 8.
        dim3 grid(8, 58);
        prep_all_kernel<<<grid, 128>>>(enc_out, W_enc, b_enc, dec_out, W_dec, W_out);
    }
    {
        dim3 grid(BT, 4);
        act_kernel<<<grid, 256>>>();
    }
    {
        dim3 grid(VV / 128, BT);   // (5, 1024)
        joint_hmma_kernel<<<grid, 128, NSTAGE * STAGE>>>(b_out, out);
    }
}

// round 14
// speedup vs baseline: 1.1568x; 1.0413x over previous
#include <cuda_runtime.h>
#include <cuda_fp16.h>
#include <math.h>
#include <stdint.h>

// ---------------- problem constants ----------------
#define BB 4
#define TT 256
#define UU 128
#define EE 512
#define DD 640
#define HH 512
#define VV 640
#define BT (BB*TT)          // 1024

// ---------------- device scratch ----------------
__device__ float g_enc_proj[BT * HH];          // [1024, 512] fp32
__device__ __half g_dec_proj_h[BB * UU * HH];  // [512, 512] fp16
__device__ __half g_A_h[BT * UU * HH];         // fp16 tanh activations (134 MB)
__device__ __half g_W_h[VV * HH];              // W_out transposed [v][h], fp16

// ---------------- PTX helpers (baseline ISA only) ----------------
__device__ __forceinline__ uint32_t smem_u32(const void* p) {
    uint32_t a;
    asm("{ .reg .u64 t; cvta.to.shared.u64 t, %1; cvt.u32.u64 %0, t; }"
        : "=r"(a) : "l"(p));
    return a;
}
__device__ __forceinline__ float tanh_fast(float x) {
    float y;
    asm("tanh.approx.f32 %0, %1;" : "=f"(y) : "f"(x));
    return y;
}
__device__ __forceinline__ void cp_async16(uint32_t dst, const void* src) {
    asm volatile("cp.async.cg.shared.global [%0], [%1], 16;"
                 :: "r"(dst), "l"(src) : "memory");
}
__device__ __forceinline__ void cp_commit() {
    asm volatile("cp.async.commit_group;" ::: "memory");
}
template <int N>
__device__ __forceinline__ void cp_wait() {
    asm volatile("cp.async.wait_group %0;" :: "n"(N) : "memory");
}
__device__ __forceinline__ void ldsm_x4(uint32_t& r0, uint32_t& r1,
                                        uint32_t& r2, uint32_t& r3, uint32_t addr) {
    asm volatile("ldmatrix.sync.aligned.m8n8.x4.shared.b16 {%0,%1,%2,%3}, [%4];"
                 : "=r"(r0), "=r"(r1), "=r"(r2), "=r"(r3) : "r"(addr));
}
__device__ __forceinline__ void mma16816(float* c, uint32_t a0, uint32_t a1,
                                         uint32_t a2, uint32_t a3,
                                         uint32_t b0, uint32_t b1) {
    asm volatile(
        "mma.sync.aligned.m16n8k16.row.col.f32.f16.f16.f32 "
        "{%0,%1,%2,%3}, {%4,%5,%6,%7}, {%8,%9}, {%0,%1,%2,%3};"
        : "+f"(c[0]), "+f"(c[1]), "+f"(c[2]), "+f"(c[3])
        : "r"(a0), "r"(a1), "r"(a2), "r"(a3), "r"(b0), "r"(b1));
}

// ---------------------------------------------------------------------------
// prep_all: ONE launch, blockIdx.y selects work.
//   y in [0,32):  enc proj (32 rows each)   -> g_enc_proj (fp32, +bias)
//   y in [32,48): dec proj                  -> g_dec_proj_h (fp16)
//   y in [48,58): W_out [H,V] -> g_W_h [V,H] fp16 transpose cast
// proj path: 32x64 tile, 128 threads, 3-stage cp.async pipeline.
// ---------------------------------------------------------------------------
__global__ __launch_bounds__(128) void prep_all_kernel(
    const float* __restrict__ enc_out, const float* __restrict__ W_enc,
    const float* __restrict__ b_enc,
    const float* __restrict__ dec_out, const float* __restrict__ W_dec,
    const float* __restrict__ W_out)
{
    int gy = blockIdx.y;

    if (gy >= 48) {
        int blk = (gy - 48) * 8 + blockIdx.x;      // 0..79
        int base = blk * 4096;
#pragma unroll
        for (int l = 0; l < 32; l++) {
            int idx = base + threadIdx.x + l * 128;
            int v = idx / HH, h = idx - v * HH;
            g_W_h[idx] = __float2half(W_out[h * VV + v]);
        }
        return;
    }

    const float* A;
    const float* W;
    int K, m0;
    bool is_enc = (gy < 32);
    if (is_enc) { A = enc_out; W = W_enc; K = EE; m0 = gy * 32; }
    else        { A = dec_out; W = W_dec; K = DD; m0 = (gy - 32) * 32; }
    int n0 = blockIdx.x * 64;
    int niter = K / 32;

    __shared__ __align__(16) float As3[3][32][36];  // [stage][m][k]
    __shared__ __align__(16) float Ws3[3][32][68];  // [stage][k][n]
    int tid = threadIdx.x;
    int tx = tid & 15, ty = tid >> 4;

    float acc[4][4];
#pragma unroll
    for (int i = 0; i < 4; i++)
#pragma unroll
        for (int j = 0; j < 4; j++) acc[i][j] = 0.0f;

    auto fillp = [&](int s, int k0) {
#pragma unroll
        for (int l = 0; l < 2; l++) {       // A: 32 rows x 8 16B-chunks
            int idx = tid + l * 128;
            int r = idx >> 3, cc = idx & 7;
            cp_async16(smem_u32(&As3[s][r][cc * 4]),
                       A + (size_t)(m0 + r) * K + k0 + cc * 4);
        }
#pragma unroll
        for (int l = 0; l < 4; l++) {       // W: 32 rows x 16 16B-chunks
            int idx = tid + l * 128;
            int r = idx >> 4, cc = idx & 15;
            cp_async16(smem_u32(&Ws3[s][r][cc * 4]),
                       W + (size_t)(k0 + r) * HH + n0 + cc * 4);
        }
    };

    fillp(0, 0);
    cp_commit();
    fillp(1, 32);
    cp_commit();

#pragma unroll 1
    for (int it = 0; it < niter; it++) {
        if (it < niter - 1) cp_wait<1>(); else cp_wait<0>();
        __syncthreads();
        if (it + 2 < niter) {
            fillp((it + 2) % 3, (it + 2) * 32);
            cp_commit();
        }
        int s = it % 3;
#pragma unroll
        for (int k = 0; k < 32; k++) {
            float a[4];
#pragma unroll
            for (int i = 0; i < 4; i++) a[i] = As3[s][ty * 4 + i][k];
            float4 bv = *(const float4*)&Ws3[s][k][tx * 4];
            float b[4] = {bv.x, bv.y, bv.z, bv.w};
#pragma unroll
            for (int i = 0; i < 4; i++)
#pragma unroll
                for (int j = 0; j < 4; j++)
                    acc[i][j] = fmaf(a[i], b[j], acc[i][j]);
        }
    }

    if (is_enc) {
#pragma unroll
        for (int i = 0; i < 4; i++)
#pragma unroll
            for (int j = 0; j < 4; j++) {
                int col = n0 + tx * 4 + j;
                g_enc_proj[(m0 + ty * 4 + i) * HH + col] = acc[i][j] + b_enc[col];
            }
    } else {
#pragma unroll
        for (int i = 0; i < 4; i++)
#pragma unroll
            for (int j = 0; j < 4; j++)
                g_dec_proj_h[(m0 + ty * 4 + i) * HH + n0 + tx * 4 + j] =
                    __float2half(acc[i][j]);
    }
}

// ---------------------------------------------------------------------------
// act: grid (BT, 4), 256 threads. enc fp32 in registers, dec read as fp16.
// ---------------------------------------------------------------------------
__global__ __launch_bounds__(256) void act_kernel()
{
    int bt = blockIdx.x;
    int b = bt >> 8;
    int ug = (threadIdx.x >> 6);
    int u0 = blockIdx.y * 32 + ug * 8;
    int h = (threadIdx.x & 63) * 8;

    const float* ep = g_enc_proj + bt * HH + h;
    float4 e0 = *(const float4*)ep;
    float4 e1 = *(const float4*)(ep + 4);

    const __half* dp = g_dec_proj_h + ((size_t)b * UU + u0) * HH + h;
    __half* ap = g_A_h + ((size_t)bt * UU + u0) * HH + h;

#pragma unroll
    for (int uu = 0; uu < 8; uu++) {
        union { uint4 u4; __half2 h2[4]; } din;
        din.u4 = *(const uint4*)(dp + (size_t)uu * HH);
        float2 d0 = __half22float2(din.h2[0]);
        float2 d1 = __half22float2(din.h2[1]);
        float2 d2 = __half22float2(din.h2[2]);
        float2 d3 = __half22float2(din.h2[3]);
        __half2 p0 = __floats2half2_rn(tanh_fast(e0.x + d0.x), tanh_fast(e0.y + d0.y));
        __half2 p1 = __floats2half2_rn(tanh_fast(e0.z + d1.x), tanh_fast(e0.w + d1.y));
        __half2 p2 = __floats2half2_rn(tanh_fast(e1.x + d2.x), tanh_fast(e1.y + d2.y));
        __half2 p3 = __floats2half2_rn(tanh_fast(e1.z + d3.x), tanh_fast(e1.w + d3.y));
        union { __half2 h2[4]; uint4 u4; } pk;
        pk.h2[0] = p0; pk.h2[1] = p1; pk.h2[2] = p2; pk.h2[3] = p3;
        *(uint4*)(ap + (size_t)uu * HH) = pk.u4;
    }
}

// ---------------------------------------------------------------------------
// joint GEMM (HMMA fp16): out[128u,128v] = A[128,512]@W^T + bias
// 4 warps (2x2), warp tile 64x64. KC=64, 3-stage cp.async, single sync/chunk,
// k-step register double-buffering (prefetch s+1 fragments during s's MMAs).
// ---------------------------------------------------------------------------
#define KC 64
#define STAGE 32768      // A 16K + W 16K
#define OFF_W 16384
#define NSTAGE 3
#define NCHUNK (HH / KC) // 8

__global__ __launch_bounds__(128, 2) void joint_hmma_kernel(
    const float* __restrict__ b_out, float* __restrict__ out)
{
    extern __shared__ char smem[];
    uint32_t sb = smem_u32(smem);
    int tid = threadIdx.x;
    int lane = tid & 31;
    int wid = tid >> 5;
    int bt = blockIdx.y;
    int v0 = blockIdx.x * 128;

    int wm = (wid & 1) * 64;
    int wn = (wid >> 1) * 64;

    const __half* Ag = g_A_h + (size_t)bt * UU * HH;
    const __half* Wg = g_W_h + (size_t)v0 * HH;

    float acc[4][8][4];
#pragma unroll
    for (int i = 0; i < 4; i++)
#pragma unroll
        for (int j = 0; j < 8; j++)
#pragma unroll
            for (int k = 0; k < 4; k++) acc[i][j][k] = 0.0f;

    auto fill = [&](int s, int k0) {
        uint32_t base = sb + s * STAGE;
#pragma unroll
        for (int l = 0; l < 8; l++) {
            int idx = tid + l * 128;
            int r = idx >> 3;
            int c = idx & 7;
            uint32_t doff = (uint32_t)(r * 128 + ((c ^ (r & 7)) << 4));
            cp_async16(base + doff,         Ag + (size_t)r * HH + k0 + c * 8);
            cp_async16(base + OFF_W + doff, Wg + (size_t)r * HH + k0 + c * 8);
        }
    };

    auto ldB = [&](uint32_t* b0, uint32_t* b1, uint32_t sW, int s) {
#pragma unroll
        for (int jj = 0; jj < 4; jj++) {
            int row = wn + jj * 16 + ((lane >> 4) & 1) * 8 + (lane & 7);
            int chunk = 2 * s + ((lane >> 3) & 1);
            ldsm_x4(b0[jj * 2], b1[jj * 2], b0[jj * 2 + 1], b1[jj * 2 + 1],
                    sW + row * 128 + ((chunk ^ (row & 7)) << 4));
        }
    };
    auto ldA = [&](uint32_t (*a)[4], uint32_t sA, int s) {
#pragma unroll
        for (int mi = 0; mi < 4; mi++) {
            int row = wm + mi * 16 + ((lane >> 3) & 1) * 8 + (lane & 7);
            int chunk = 2 * s + (lane >> 4);
            ldsm_x4(a[mi][0], a[mi][1], a[mi][2], a[mi][3],
                    sA + row * 128 + ((chunk ^ (row & 7)) << 4));
        }
    };

    fill(0, 0);
    cp_commit();
    fill(1, KC);
    cp_commit();

#pragma unroll 1
    for (int c = 0; c < NCHUNK; c++) {
        if (c < NCHUNK - 1) cp_wait<1>(); else cp_wait<0>();
        __syncthreads();
        if (c + 2 < NCHUNK) {
            fill((c + 2) % NSTAGE, (c + 2) * KC);
            cp_commit();
        }

        uint32_t sA = sb + (c % NSTAGE) * STAGE;
        uint32_t sW = sA + OFF_W;

        uint32_t bf0[2][8], bf1[2][8], af[2][4][4];
        ldB(bf0[0], bf1[0], sW, 0);
        ldA(af[0], sA, 0);

#pragma unroll
        for (int s = 0; s < 4; s++) {
            int cur = s & 1;
            if (s < 3) {
                ldB(bf0[cur ^ 1], bf1[cur ^ 1], sW, s + 1);
                ldA(af[cur ^ 1], sA, s + 1);
            }
#pragma unroll
            for (int mi = 0; mi < 4; mi++)
#pragma unroll
                for (int ni = 0; ni < 8; ni++)
                    mma16816(acc[mi][ni], af[cur][mi][0], af[cur][mi][1],
                             af[cur][mi][2], af[cur][mi][3],
                             bf0[cur][ni], bf1[cur][ni]);
        }
    }

    // ---- epilogue ----
    int gid = lane >> 2;
    int tig = lane & 3;
    float2 bias2[8];
#pragma unroll
    for (int ni = 0; ni < 8; ni++)
        bias2[ni] = *(const float2*)(b_out + v0 + wn + ni * 8 + tig * 2);

    float* obase = out + (size_t)bt * UU * VV + v0;
#pragma unroll
    for (int mi = 0; mi < 4; mi++) {
        int u0 = wm + mi * 16 + gid;
#pragma unroll
        for (int ni = 0; ni < 8; ni++) {
            int v = wn + ni * 8 + tig * 2;
            float2 r0 = make_float2(acc[mi][ni][0] + bias2[ni].x,
                                    acc[mi][ni][1] + bias2[ni].y);
            float2 r1 = make_float2(acc[mi][ni][2] + bias2[ni].x,
                                    acc[mi][ni][3] + bias2[ni].y);
            *(float2*)(obase + (size_t)u0 * VV + v) = r0;
            *(float2*)(obase + (size_t)(u0 + 8) * VV + v) = r1;
        }
    }
}

// ---------------------------------------------------------------------------
extern "C" void kernel_launch(void* const* d_in, const int* in_sizes, int n_in,
                              void* d_out, int out_size)
{
    const float* enc_out = (const float*)d_in[0];
    const float* dec_out = (const float*)d_in[1];
    const float* W_enc   = (const float*)d_in[2];
    const float* b_enc   = (const float*)d_in[3];
    const float* W_dec   = (const float*)d_in[4];
    const float* W_out   = (const float*)d_in[5];
    const float* b_out   = (const float*)d_in[6];
    float* out = (float*)d_out;

    cudaFuncSetAttribute(joint_hmma_kernel,
                         cudaFuncAttributeMaxDynamicSharedMemorySize, NSTAGE * STAGE);

    {
        dim3 grid(8, 58);
        prep_all_kernel<<<grid, 128>>>(enc_out, W_enc, b_enc, dec_out, W_dec, W_out);
    }
    {
        dim3 grid(BT, 4);
        act_kernel<<<grid, 256>>>();
    }
    {
        dim3 grid(VV / 128, BT);   // (5, 1024)
        joint_hmma_kernel<<<grid, 128, NSTAGE * STAGE>>>(b_out, out);
    }
}